// round 15
// baseline (speedup 1.0000x reference)
#include <cuda_runtime.h>
#include <math.h>
#include <stdint.h>

#define BB 16
#define DD 2048
#define NH 32
#define NKV 8
#define HDIM 64
#define GRP 4
#define TSEQ 4096
#define HIDDEN 5632
#define KVD 512
#define NSPLIT 32
#define TCHUNK 128
#define QKVD 3072

// ---------------- scratch ----------------
__device__ float g_xn[BB * DD];
__device__ float g_q[BB * DD];
__device__ float g_k[BB * KVD];
__device__ float g_v[BB * KVD];
__device__ float g_attn[BB * DD];
__device__ float g_h[BB * DD];
__device__ float g_hn[BB * DD];
__device__ float g_ff1[BB * HIDDEN];
__device__ float g_qkp[2][BB * QKVD];
__device__ float g_wop[2][BB * DD];
__device__ float g_w1p[2][BB * HIDDEN];
__device__ float g_w2p[4][BB * DD];
__device__ float g_w3p[2][BB * DD];
__device__ float g_po[BB * NKV * NSPLIT * GRP * HDIM];
__device__ float g_pl[BB * NKV * NSPLIT * GRP];

__device__ __forceinline__ float warp_sum(float v) {
    v += __shfl_down_sync(0xffffffffu, v, 16);
    v += __shfl_down_sync(0xffffffffu, v, 8);
    v += __shfl_down_sync(0xffffffffu, v, 4);
    v += __shfl_down_sync(0xffffffffu, v, 2);
    v += __shfl_down_sync(0xffffffffu, v, 1);
    return v;
}

// ---- f32x2 packed-FMA helpers ----
__device__ __forceinline__ unsigned long long pack2(float v) {
    unsigned long long r;
    asm("mov.b64 %0, {%1, %1};" : "=l"(r) : "f"(v));
    return r;
}
__device__ __forceinline__ void fma2(unsigned long long& acc,
                                     unsigned long long a,
                                     unsigned long long b) {
    asm("fma.rn.f32x2 %0, %1, %2, %3;" : "=l"(acc) : "l"(a), "l"(b), "l"(acc));
}
__device__ __forceinline__ float2 unpack2(unsigned long long v) {
    float2 r;
    asm("mov.b64 {%0, %1}, %2;" : "=f"(r.x), "=f"(r.y) : "l"(v));
    return r;
}

// ============ 16-batch staged GEMV core (partial over K range) ============
// CTA: 16 rows x 16 batches x KR cols [k0, k0+KR). 256 thr.
// Warp w owns rows row0+2w, row0+2w+1, scans full KR. acc[8 pairs][2 rows].
// Output: thread tid -> batch tid>>4, row offset tid&15.
template <int KR>
__device__ __forceinline__ float gemv16(const float* __restrict__ A,
                                        const float* __restrict__ W,
                                        int K, int k0, int row0, int tid,
                                        int* pb, int* prr) {
    extern __shared__ float dyn[];
    constexpr int KR4 = KR / 4;
    constexpr int STEPS = KR4 / 32;
    float* a_lo = dyn;                    // 8 pairs * KR4 float4 = 8*KR floats
    float* a_hi = dyn + 8 * KR;
    float* s_part = dyn + 16 * KR;        // [8][16][2]

    // stage 16 batches interleaved by pair
    {
        float4* lo4 = (float4*)a_lo;
        float4* hi4 = (float4*)a_hi;
        for (int idx = tid; idx < 8 * KR4; idx += 256) {
            int p = idx / KR4, c = idx - p * KR4;
            const float* base = A + (size_t)(2 * p) * K + k0 + 4 * c;
            float4 a = *(const float4*)base;
            float4 b = *(const float4*)(base + K);
            lo4[idx] = make_float4(a.x, b.x, a.y, b.y);
            hi4[idx] = make_float4(a.z, b.z, a.w, b.w);
        }
    }
    __syncthreads();

    int lane = tid & 31, w = tid >> 5;
    const float4* wp0 = (const float4*)(W + (size_t)(row0 + 2 * w) * K + k0);
    const float4* wp1 = (const float4*)(W + (size_t)(row0 + 2 * w + 1) * K + k0);
    const ulonglong2* lo2 = (const ulonglong2*)a_lo;
    const ulonglong2* hi2 = (const ulonglong2*)a_hi;

    unsigned long long acc[8][2];
#pragma unroll
    for (int p = 0; p < 8; p++) { acc[p][0] = 0ull; acc[p][1] = 0ull; }

    int cc = lane;
    float4 wbuf[3][2];
#pragma unroll
    for (int s = 0; s < 2 && s < STEPS; s++) {
        wbuf[s][0] = __ldcs(wp0 + cc + s * 32);
        wbuf[s][1] = __ldcs(wp1 + cc + s * 32);
    }
#pragma unroll
    for (int s = 0; s < STEPS; s++) {
        if (s + 2 < STEPS) {
            wbuf[(s + 2) % 3][0] = __ldcs(wp0 + cc + (s + 2) * 32);
            wbuf[(s + 2) % 3][1] = __ldcs(wp1 + cc + (s + 2) * 32);
        }
        ulonglong2 xa[8], xb[8];
#pragma unroll
        for (int p = 0; p < 8; p++) {
            xa[p] = lo2[p * KR4 + cc + s * 32];
            xb[p] = hi2[p * KR4 + cc + s * 32];
        }
#pragma unroll
        for (int r = 0; r < 2; r++) {
            float4 wr = wbuf[s % 3][r];
            unsigned long long q0 = pack2(wr.x), q1 = pack2(wr.y);
            unsigned long long q2 = pack2(wr.z), q3 = pack2(wr.w);
#pragma unroll
            for (int p = 0; p < 8; p++) {
                fma2(acc[p][r], q0, xa[p].x);
                fma2(acc[p][r], q1, xa[p].y);
                fma2(acc[p][r], q2, xb[p].x);
                fma2(acc[p][r], q3, xb[p].y);
            }
        }
    }
#pragma unroll
    for (int p = 0; p < 8; p++)
#pragma unroll
        for (int r = 0; r < 2; r++) {
            float2 f = unpack2(acc[p][r]);
            float sx = warp_sum(f.x);
            float sy = warp_sum(f.y);
            if (lane == 0) {
                s_part[w * 32 + (2 * p) * 2 + r] = sx;
                s_part[w * 32 + (2 * p + 1) * 2 + r] = sy;
            }
        }
    __syncthreads();
    int b = tid >> 4, rr = tid & 15;
    *pb = b; *prr = rr;
    return s_part[(rr >> 1) * 32 + b * 2 + (rr & 1)];
}

// ---------------- rmsnorm (x -> g_xn) ----------------
__global__ void rmsnorm_x_kernel(const float* __restrict__ x,
                                 const float* __restrict__ w) {
    int b = blockIdx.x;
    const float* xr = x + (size_t)b * DD;
    float s = 0.f;
    for (int i = threadIdx.x; i < DD; i += 512) { float v = xr[i]; s += v * v; }
    for (int off = 16; off; off >>= 1) s += __shfl_xor_sync(0xffffffffu, s, off);
    __shared__ float red[16];
    int lane = threadIdx.x & 31, wid = threadIdx.x >> 5;
    if (lane == 0) red[wid] = s;
    __syncthreads();
    if (threadIdx.x == 0) {
        float t = 0.f;
#pragma unroll
        for (int i = 0; i < 16; i++) t += red[i];
        red[0] = rsqrtf(t * (1.0f / DD) + 1e-6f);
    }
    __syncthreads();
    float inv = red[0];
    float* orow = g_xn + (size_t)b * DD;
    for (int i = threadIdx.x; i < DD; i += 512) orow[i] = xr[i] * inv * w[i];
}

// ---------------- combined: h = x + wo-partials; hn = rmsnorm(h) -----------
__global__ void rmsnorm_h_comb_kernel(const float* __restrict__ x,
                                      const float* __restrict__ w) {
    int b = blockIdx.x;
    const float* xr = x + (size_t)b * DD;
    const float* p0 = g_wop[0] + (size_t)b * DD;
    const float* p1 = g_wop[1] + (size_t)b * DD;
    float* hrow = g_h + (size_t)b * DD;
    float s = 0.f;
    for (int i = threadIdx.x; i < DD; i += 512) {
        float hv = xr[i] + p0[i] + p1[i];
        hrow[i] = hv;
        s += hv * hv;
    }
    for (int off = 16; off; off >>= 1) s += __shfl_xor_sync(0xffffffffu, s, off);
    __shared__ float red[16];
    int lane = threadIdx.x & 31, wid = threadIdx.x >> 5;
    if (lane == 0) red[wid] = s;
    __syncthreads();
    if (threadIdx.x == 0) {
        float t = 0.f;
#pragma unroll
        for (int i = 0; i < 16; i++) t += red[i];
        red[0] = rsqrtf(t * (1.0f / DD) + 1e-6f);
    }
    __syncthreads();
    float inv = red[0];
    float* orow = g_hn + (size_t)b * DD;
    for (int i = threadIdx.x; i < DD; i += 512) orow[i] = hrow[i] * inv * w[i];
}

// ---------------- GEMV kernels (K-split partials) ----------------
__global__ __launch_bounds__(256, 2) void gemv_qkv_kernel(
    const float* __restrict__ wq, const float* __restrict__ wk,
    const float* __restrict__ wv) {
    int bi = blockIdx.x;
    int kh = bi & 1, row0 = (bi >> 1) * 16;
    const float* Wm; int wrow0;
    if (row0 < 2048)      { Wm = wq; wrow0 = row0; }
    else if (row0 < 2560) { Wm = wk; wrow0 = row0 - 2048; }
    else                  { Wm = wv; wrow0 = row0 - 2560; }
    int b, rr;
    float v = gemv16<1024>(g_xn, Wm, DD, kh * 1024, wrow0, threadIdx.x, &b, &rr);
    g_qkp[kh][(size_t)b * QKVD + row0 + rr] = v;
}

// combine qkv partials + RoPE (applied to q, k, v)
__global__ void combine_qkv_rope_kernel(const float* __restrict__ cosv,
                                        const float* __restrict__ sinv) {
    int idx = blockIdx.x * 256 + threadIdx.x;     // pair index: 16*1536
    if (idx >= BB * (QKVD / 2)) return;
    int b = idx / (QKVD / 2);
    int i = idx - b * (QKVD / 2);
    int row = 2 * i;
    size_t off = (size_t)b * QKVD + row;
    float v0 = g_qkp[0][off] + g_qkp[1][off];
    float v1 = g_qkp[0][off + 1] + g_qkp[1][off + 1];
    int ri = i & 31;
    float c = cosv[ri], s = sinv[ri];
    float o0 = v0 * c - v1 * s;
    float o1 = v0 * s + v1 * c;
    if (row < 2048) {
        g_q[(size_t)b * DD + row] = o0;
        g_q[(size_t)b * DD + row + 1] = o1;
    } else if (row < 2560) {
        g_k[(size_t)b * KVD + row - 2048] = o0;
        g_k[(size_t)b * KVD + row - 2047] = o1;
    } else {
        g_v[(size_t)b * KVD + row - 2560] = o0;
        g_v[(size_t)b * KVD + row - 2559] = o1;
    }
}

__global__ __launch_bounds__(256, 2) void gemv_wo_kernel(const float* __restrict__ wo) {
    int bi = blockIdx.x;
    int kh = bi & 1, row0 = (bi >> 1) * 16;
    int b, rr;
    float v = gemv16<1024>(g_attn, wo, DD, kh * 1024, row0, threadIdx.x, &b, &rr);
    g_wop[kh][(size_t)b * DD + row0 + rr] = v;
}

__global__ __launch_bounds__(256, 2) void gemv_w1_kernel(const float* __restrict__ w1) {
    int bi = blockIdx.x;
    int kh = bi & 1, row0 = (bi >> 1) * 16;
    int b, rr;
    float v = gemv16<1024>(g_hn, w1, DD, kh * 1024, row0, threadIdx.x, &b, &rr);
    g_w1p[kh][(size_t)b * HIDDEN + row0 + rr] = v;
}

__global__ void combine_w1_silu_kernel() {
    int idx = blockIdx.x * 256 + threadIdx.x;
    if (idx >= BB * HIDDEN) return;
    float v = g_w1p[0][idx] + g_w1p[1][idx];
    g_ff1[idx] = v / (1.0f + __expf(-v));
}

__global__ __launch_bounds__(256, 2) void gemv_w2_kernel(const float* __restrict__ w2) {
    int bi = blockIdx.x;
    int kq = bi & 3, row0 = (bi >> 2) * 16;
    int b, rr;
    float v = gemv16<1408>(g_ff1, w2, HIDDEN, kq * 1408, row0, threadIdx.x, &b, &rr);
    g_w2p[kq][(size_t)b * DD + row0 + rr] = v;
}

__global__ __launch_bounds__(256, 2) void gemv_w3_kernel(const float* __restrict__ w3) {
    int bi = blockIdx.x;
    int kh = bi & 1, row0 = (bi >> 1) * 16;
    int b, rr;
    float v = gemv16<1024>(g_hn, w3, DD, kh * 1024, row0, threadIdx.x, &b, &rr);
    g_w3p[kh][(size_t)b * DD + row0 + rr] = v;
}

__global__ void final_kernel(float* __restrict__ out) {
    int idx = blockIdx.x * 256 + threadIdx.x;
    if (idx >= BB * DD) return;
    out[idx] = g_h[idx] + g_w3p[0][idx] + g_w3p[1][idx] +
               g_w2p[0][idx] + g_w2p[1][idx] + g_w2p[2][idx] + g_w2p[3][idx];
}

// ---------------- attention split kernel (proven R13 version) --------------
__global__ __launch_bounds__(256) void attn_split_kernel(
    const float* __restrict__ cache_k, const float* __restrict__ cache_v) {
    int blk = blockIdx.x;
    int pair = blk / NSPLIT, split = blk % NSPLIT;
    int b = pair >> 3, kv = pair & 7;
    int t0 = split * TCHUNK;
    int tid = threadIdx.x, lane = tid & 31, wid = tid >> 5;

    __shared__ float q_s[4][64];
    __shared__ float4 e_sT[TCHUNK];
    __shared__ float red[4][8];
    __shared__ float o_part[4][4][64];

    {
        int g = tid >> 6, d = tid & 63;
        q_s[g][d] = g_q[(size_t)b * DD + (kv * 4 + g) * 64 + d] * 0.125f;
    }
    __syncthreads();

    int c = lane & 7, p = lane >> 3;
    float qr[4][8];
#pragma unroll
    for (int g = 0; g < 4; g++)
#pragma unroll
        for (int j = 0; j < 8; j++) qr[g][j] = q_s[g][c * 8 + j];

    const float* kbase = cache_k + ((size_t)b * TSEQ * NKV + kv) * HDIM;
    const float* knew  = g_k + (size_t)(b * NKV + kv) * HDIM;

    float esum[4] = {0.f, 0.f, 0.f, 0.f};
#pragma unroll
    for (int it = 0; it < TCHUNK / 32; it++) {
        int tl = it * 32 + wid * 4 + p;
        int t = t0 + tl;
        const float* krow = (t < TSEQ - 1) ? (kbase + (size_t)t * KVD) : knew;
        const float4* k4 = (const float4*)krow;
        float4 k0 = __ldcs(k4 + c * 2);
        float4 k1 = __ldcs(k4 + c * 2 + 1);
        float kv8[8] = {k0.x, k0.y, k0.z, k0.w, k1.x, k1.y, k1.z, k1.w};
        float a0 = 0.f, a1 = 0.f, a2 = 0.f, a3 = 0.f;
#pragma unroll
        for (int j = 0; j < 8; j++) {
            a0 += qr[0][j] * kv8[j];
            a1 += qr[1][j] * kv8[j];
            a2 += qr[2][j] * kv8[j];
            a3 += qr[3][j] * kv8[j];
        }
#pragma unroll
        for (int off = 1; off <= 4; off <<= 1) {
            a0 += __shfl_xor_sync(0xffffffffu, a0, off);
            a1 += __shfl_xor_sync(0xffffffffu, a1, off);
            a2 += __shfl_xor_sync(0xffffffffu, a2, off);
            a3 += __shfl_xor_sync(0xffffffffu, a3, off);
        }
        if (c == 0) {
            float4 e;
            e.x = __expf(a0); e.y = __expf(a1);
            e.z = __expf(a2); e.w = __expf(a3);
            e_sT[tl] = e;
            esum[0] += e.x; esum[1] += e.y; esum[2] += e.z; esum[3] += e.w;
        }
    }
#pragma unroll
    for (int g = 0; g < 4; g++) {
        esum[g] = warp_sum(esum[g]);
        if (lane == 0) red[g][wid] = esum[g];
    }
    __syncthreads();
    if (tid < 4) {
        float s = 0.f;
#pragma unroll
        for (int w = 0; w < 8; w++) s += red[tid][w];
        g_pl[blk * 4 + tid] = s;
    }

    {
        int qq = tid >> 6, d = tid & 63;
        const float* vcol = cache_v + ((size_t)b * TSEQ * NKV + kv) * HDIM + d;
        const float* vnew = g_v + (size_t)(b * NKV + kv) * HDIM + d;
        float o0 = 0.f, o1 = 0.f, o2 = 0.f, o3 = 0.f;
        int tlb = qq * (TCHUNK / 4);
#pragma unroll 8
        for (int i = 0; i < TCHUNK / 4; i++) {
            int tl = tlb + i;
            int t = t0 + tl;
            float v = (t < TSEQ - 1) ? __ldcs(vcol + (size_t)t * KVD) : *vnew;
            float4 pv = e_sT[tl];
            o0 += pv.x * v; o1 += pv.y * v; o2 += pv.z * v; o3 += pv.w * v;
        }
        o_part[qq][0][d] = o0;
        o_part[qq][1][d] = o1;
        o_part[qq][2][d] = o2;
        o_part[qq][3][d] = o3;
    }
    __syncthreads();
    {
        int g = tid >> 6, d = tid & 63;
        float sum = o_part[0][g][d] + o_part[1][g][d] +
                    o_part[2][g][d] + o_part[3][g][d];
        g_po[(size_t)blk * 256 + g * 64 + d] = sum;
    }
}

// ---------------- parallel reduce ----------------
__global__ __launch_bounds__(128) void attn_reduce_kernel() {
    int pg = blockIdx.x;
    int pair = pg >> 2, g = pg & 3;
    int b = pair >> 3, kv = pair & 7;
    int tid = threadIdx.x, d = tid & 63, sh = tid >> 6;
    __shared__ float s_o[2][64];
    __shared__ float s_l[2];
    float l = 0.f, o = 0.f;
#pragma unroll
    for (int i = 0; i < NSPLIT / 2; i++) {
        int s = sh * (NSPLIT / 2) + i;
        int bs = pair * NSPLIT + s;
        l += g_pl[bs * 4 + g];
        o += g_po[(size_t)bs * 256 + g * 64 + d];
    }
    s_o[sh][d] = o;
    if (d == 0) s_l[sh] = l;
    __syncthreads();
    if (sh == 0) {
        float L = s_l[0] + s_l[1];
        float O = o + s_o[1][d];
        g_attn[(size_t)b * DD + (kv * 4 + g) * 64 + d] = O / L;
    }
}

// ---------------- launch ----------------
extern "C" void kernel_launch(void* const* d_in, const int* in_sizes, int n_in,
                              void* d_out, int out_size) {
    const float* x         = (const float*)d_in[0];
    const float* freqs_cos = (const float*)d_in[1];
    const float* freqs_sin = (const float*)d_in[2];
    const float* cache_k   = (const float*)d_in[3];
    const float* cache_v   = (const float*)d_in[4];
    const float* wq_w      = (const float*)d_in[5];
    const float* wk_w      = (const float*)d_in[6];
    const float* wv_w      = (const float*)d_in[7];
    const float* wo_w      = (const float*)d_in[8];
    const float* w1_w      = (const float*)d_in[9];
    const float* w2_w      = (const float*)d_in[10];
    const float* w3_w      = (const float*)d_in[11];
    const float* attn_nw   = (const float*)d_in[12];
    const float* ffn_nw    = (const float*)d_in[13];
    float* out = (float*)d_out;

    const int SMEM_1024 = (16 * 1024 + 256) * 4;   // 66560
    const int SMEM_1408 = (16 * 1408 + 256) * 4;   // 91136
    cudaFuncSetAttribute(gemv_qkv_kernel, cudaFuncAttributeMaxDynamicSharedMemorySize, SMEM_1024);
    cudaFuncSetAttribute(gemv_wo_kernel,  cudaFuncAttributeMaxDynamicSharedMemorySize, SMEM_1024);
    cudaFuncSetAttribute(gemv_w1_kernel,  cudaFuncAttributeMaxDynamicSharedMemorySize, SMEM_1024);
    cudaFuncSetAttribute(gemv_w2_kernel,  cudaFuncAttributeMaxDynamicSharedMemorySize, SMEM_1408);
    cudaFuncSetAttribute(gemv_w3_kernel,  cudaFuncAttributeMaxDynamicSharedMemorySize, SMEM_1024);

    rmsnorm_x_kernel<<<BB, 512>>>(x, attn_nw);
    gemv_qkv_kernel<<<(QKVD / 16) * 2, 256, SMEM_1024>>>(wq_w, wk_w, wv_w);
    combine_qkv_rope_kernel<<<(BB * (QKVD / 2) + 255) / 256, 256>>>(freqs_cos, freqs_sin);
    attn_split_kernel<<<BB * NKV * NSPLIT, 256>>>(cache_k, cache_v);
    attn_reduce_kernel<<<BB * NKV * GRP, 128>>>();
    gemv_wo_kernel<<<(DD / 16) * 2, 256, SMEM_1024>>>(wo_w);
    rmsnorm_h_comb_kernel<<<BB, 512>>>(x, ffn_nw);
    gemv_w1_kernel<<<(HIDDEN / 16) * 2, 256, SMEM_1024>>>(w1_w);
    combine_w1_silu_kernel<<<(BB * HIDDEN + 255) / 256, 256>>>();
    gemv_w2_kernel<<<(DD / 16) * 4, 256, SMEM_1408>>>(w2_w);
    gemv_w3_kernel<<<(DD / 16) * 2, 256, SMEM_1024>>>(w3_w);
    final_kernel<<<(BB * DD + 255) / 256, 256>>>(out);
}

// round 16
// speedup vs baseline: 1.0897x; 1.0897x over previous
#include <cuda_runtime.h>
#include <math.h>
#include <stdint.h>

#define BB 16
#define DD 2048
#define NH 32
#define NKV 8
#define HDIM 64
#define GRP 4
#define TSEQ 4096
#define HIDDEN 5632
#define KVD 512
#define NSPLIT 32
#define TCHUNK 128

// ---------------- scratch ----------------
__device__ float g_inv[BB];
__device__ float g_q[BB * DD];
__device__ float g_k[BB * KVD];
__device__ float g_v[BB * KVD];
__device__ float g_attn[BB * DD];
__device__ float g_h[BB * DD];
__device__ float g_hn[BB * DD];
__device__ float g_ff1[BB * HIDDEN];
__device__ float g_w2p[2][BB * DD];
__device__ float g_w3o[BB * DD];
__device__ float g_po[BB * NKV * NSPLIT * GRP * HDIM];   // 4 MB
__device__ float g_pl[BB * NKV * NSPLIT * GRP];

__device__ __forceinline__ float warp_sum(float v) {
    v += __shfl_down_sync(0xffffffffu, v, 16);
    v += __shfl_down_sync(0xffffffffu, v, 8);
    v += __shfl_down_sync(0xffffffffu, v, 4);
    v += __shfl_down_sync(0xffffffffu, v, 2);
    v += __shfl_down_sync(0xffffffffu, v, 1);
    return v;
}

// ---- f32x2 packed-FMA helpers (B300 dual-issue FMA; PTX-only) ----
__device__ __forceinline__ unsigned long long pack2(float v) {
    unsigned long long r;
    asm("mov.b64 %0, {%1, %1};" : "=l"(r) : "f"(v));
    return r;
}
__device__ __forceinline__ void fma2(unsigned long long& acc,
                                     unsigned long long a,
                                     unsigned long long b) {
    asm("fma.rn.f32x2 %0, %1, %2, %3;" : "=l"(acc) : "l"(a), "l"(b), "l"(acc));
}
__device__ __forceinline__ float2 unpack2(unsigned long long v) {
    float2 r;
    asm("mov.b64 {%0, %1}, %2;" : "=f"(r.x), "=f"(r.y) : "l"(v));
    return r;
}

// ============ staged GEMV core: f32x2 FMA + depth-2 weight pipeline ============
// CTA: 16 rows x 8 batches (4 f32x2 pairs) x KR cols, 256 thr.
// NORM: stage A as A*g_inv[b]*nw[col] (fused rmsnorm).
template <int KR, bool NORM>
__device__ __forceinline__ bool gemv_staged(const float* __restrict__ A,
                                            const float* __restrict__ W,
                                            const float* __restrict__ nw,
                                            int K, int k0, int row0, int bh,
                                            int tid,
                                            int* pb, int* prr, float* pv) {
    extern __shared__ float dyn[];
    constexpr int KR4 = KR / 4;
    float* a_lo = dyn;                       // 4*KR floats
    float* a_hi = dyn + 4 * KR;              // 4*KR floats
    float* s_part = dyn + 8 * KR;            // [8][8][4]
    constexpr int PER = KR4 / 2;
    constexpr int STEPS = PER / 32;

    {
        const float* Ab = A + (size_t)bh * 8 * K + k0;
        float4* lo4 = (float4*)a_lo;
        float4* hi4 = (float4*)a_hi;
        for (int idx = tid; idx < KR; idx += 256) {
            int p = idx / KR4, c = idx - p * KR4;
            const float* base = Ab + (size_t)(2 * p) * K + 4 * c;
            float4 a = *(const float4*)base;
            float4 b = *(const float4*)(base + K);
            if (NORM) {
                float ia = g_inv[bh * 8 + 2 * p];
                float ib = g_inv[bh * 8 + 2 * p + 1];
                float4 wv = *(const float4*)(nw + k0 + 4 * c);
                a.x *= ia * wv.x; a.y *= ia * wv.y;
                a.z *= ia * wv.z; a.w *= ia * wv.w;
                b.x *= ib * wv.x; b.y *= ib * wv.y;
                b.z *= ib * wv.z; b.w *= ib * wv.w;
            }
            lo4[idx] = make_float4(a.x, b.x, a.y, b.y);
            hi4[idx] = make_float4(a.z, b.z, a.w, b.w);
        }
    }
    __syncthreads();

    int lane = tid & 31, w = tid >> 5;
    int rq = w & 3, kh = w >> 2;
    int c0 = kh * PER;
    const float4* wp0 = (const float4*)(W + (size_t)(row0 + rq * 4 + 0) * K + k0);
    const float4* wp1 = (const float4*)(W + (size_t)(row0 + rq * 4 + 1) * K + k0);
    const float4* wp2 = (const float4*)(W + (size_t)(row0 + rq * 4 + 2) * K + k0);
    const float4* wp3 = (const float4*)(W + (size_t)(row0 + rq * 4 + 3) * K + k0);
    const ulonglong2* lo2 = (const ulonglong2*)a_lo;
    const ulonglong2* hi2 = (const ulonglong2*)a_hi;

    unsigned long long acc[4][4];
#pragma unroll
    for (int p = 0; p < 4; p++)
#pragma unroll
        for (int r = 0; r < 4; r++) acc[p][r] = 0ull;

    int cc = c0 + lane;
    float4 wbuf[3][4];
#pragma unroll
    for (int s = 0; s < 2 && s < STEPS; s++) {
        wbuf[s][0] = __ldcs(wp0 + cc + s * 32);
        wbuf[s][1] = __ldcs(wp1 + cc + s * 32);
        wbuf[s][2] = __ldcs(wp2 + cc + s * 32);
        wbuf[s][3] = __ldcs(wp3 + cc + s * 32);
    }
#pragma unroll
    for (int s = 0; s < STEPS; s++) {
        if (s + 2 < STEPS) {
            wbuf[(s + 2) % 3][0] = __ldcs(wp0 + cc + (s + 2) * 32);
            wbuf[(s + 2) % 3][1] = __ldcs(wp1 + cc + (s + 2) * 32);
            wbuf[(s + 2) % 3][2] = __ldcs(wp2 + cc + (s + 2) * 32);
            wbuf[(s + 2) % 3][3] = __ldcs(wp3 + cc + (s + 2) * 32);
        }
        ulonglong2 xa[4], xb[4];
#pragma unroll
        for (int p = 0; p < 4; p++) {
            xa[p] = lo2[p * KR4 + cc + s * 32];
            xb[p] = hi2[p * KR4 + cc + s * 32];
        }
#pragma unroll
        for (int r = 0; r < 4; r++) {
            float4 wr = wbuf[s % 3][r];
            unsigned long long q0 = pack2(wr.x), q1 = pack2(wr.y);
            unsigned long long q2 = pack2(wr.z), q3 = pack2(wr.w);
#pragma unroll
            for (int p = 0; p < 4; p++) {
                fma2(acc[p][r], q0, xa[p].x);
                fma2(acc[p][r], q1, xa[p].y);
                fma2(acc[p][r], q2, xb[p].x);
                fma2(acc[p][r], q3, xb[p].y);
            }
        }
    }
#pragma unroll
    for (int p = 0; p < 4; p++)
#pragma unroll
        for (int r = 0; r < 4; r++) {
            float2 f = unpack2(acc[p][r]);
            float sx = warp_sum(f.x);
            float sy = warp_sum(f.y);
            if (lane == 0) {
                s_part[w * 32 + (2 * p) * 4 + r] = sx;
                s_part[w * 32 + (2 * p + 1) * 4 + r] = sy;
            }
        }
    __syncthreads();
    if (tid < 128) {
        int b8 = tid >> 4, rr = tid & 15;
        int rq2 = rr >> 2, r2 = rr & 3;
        *pb = bh * 8 + b8;
        *prr = rr;
        *pv = s_part[rq2 * 32 + b8 * 4 + r2] + s_part[(4 + rq2) * 32 + b8 * 4 + r2];
        return true;
    }
    return false;
}

// ---------------- sumsq for fused rmsnorm_x ----------------
__global__ void sumsq_x_kernel(const float* __restrict__ x) {
    int b = blockIdx.x;
    const float* xr = x + (size_t)b * DD;
    float s = 0.f;
    for (int i = threadIdx.x; i < DD; i += 512) { float v = xr[i]; s += v * v; }
    for (int off = 16; off; off >>= 1) s += __shfl_xor_sync(0xffffffffu, s, off);
    __shared__ float red[16];
    int lane = threadIdx.x & 31, wid = threadIdx.x >> 5;
    if (lane == 0) red[wid] = s;
    __syncthreads();
    if (threadIdx.x == 0) {
        float t = 0.f;
#pragma unroll
        for (int i = 0; i < 16; i++) t += red[i];
        g_inv[b] = rsqrtf(t * (1.0f / DD) + 1e-6f);
    }
}

// ---------------- rmsnorm h -> hn ----------------
__global__ void rmsnorm_h_kernel(const float* __restrict__ w) {
    int b = blockIdx.x;
    const float* xr = g_h + (size_t)b * DD;
    float s = 0.f;
    for (int i = threadIdx.x; i < DD; i += 512) { float v = xr[i]; s += v * v; }
    for (int off = 16; off; off >>= 1) s += __shfl_xor_sync(0xffffffffu, s, off);
    __shared__ float red[16];
    int lane = threadIdx.x & 31, wid = threadIdx.x >> 5;
    if (lane == 0) red[wid] = s;
    __syncthreads();
    if (threadIdx.x == 0) {
        float t = 0.f;
#pragma unroll
        for (int i = 0; i < 16; i++) t += red[i];
        red[0] = rsqrtf(t * (1.0f / DD) + 1e-6f);
    }
    __syncthreads();
    float inv = red[0];
    float* orow = g_hn + (size_t)b * DD;
    for (int i = threadIdx.x; i < DD; i += 512) orow[i] = xr[i] * inv * w[i];
}

// ---------------- GEMV kernels ----------------
__global__ __launch_bounds__(256, 2) void gemv_qkv_kernel(
    const float* __restrict__ x, const float* __restrict__ anw,
    const float* __restrict__ wq, const float* __restrict__ wk,
    const float* __restrict__ wv, const float* __restrict__ cosv,
    const float* __restrict__ sinv) {
    int bi = blockIdx.x;
    int bh = bi & 1, row0 = (bi >> 1) * 16;
    const float* Wm; int wrow0;
    if (row0 < 2048)      { Wm = wq; wrow0 = row0; }
    else if (row0 < 2560) { Wm = wk; wrow0 = row0 - 2048; }
    else                  { Wm = wv; wrow0 = row0 - 2560; }
    int b, rr; float v = 0.f;
    bool valid = gemv_staged<2048, true>(x, Wm, anw, DD, 0, wrow0, bh,
                                         threadIdx.x, &b, &rr, &v);
    float vp = __shfl_xor_sync(0xffffffffu, v, 1);
    if (valid) {
        int row = wrow0 + rr;
        int i = (row & 63) >> 1;
        float cc = cosv[i], ss = sinv[i];
        float res = (rr & 1) ? (vp * ss + v * cc) : (v * cc - vp * ss);
        if (row0 < 2048)      g_q[(size_t)b * DD + row] = res;
        else if (row0 < 2560) g_k[(size_t)b * KVD + row] = res;
        else                  g_v[(size_t)b * KVD + row] = res;
    }
}

__global__ __launch_bounds__(256, 2) void gemv_wo_kernel(
    const float* __restrict__ wo, const float* __restrict__ x) {
    int bi = blockIdx.x;
    int bh = bi & 1, row0 = (bi >> 1) * 16;
    int b, rr; float v;
    if (gemv_staged<2048, false>(g_attn, wo, 0, DD, 0, row0, bh, threadIdx.x,
                                 &b, &rr, &v)) {
        int row = row0 + rr;
        g_h[(size_t)b * DD + row] = v + x[(size_t)b * DD + row];
    }
}

// merged w1 (silu) + w3: both read g_hn
__global__ __launch_bounds__(256, 2) void gemv_w1w3_kernel(
    const float* __restrict__ w1, const float* __restrict__ w3) {
    int bi = blockIdx.x;
    if (bi < (HIDDEN / 16) * 2) {
        int bh = bi & 1, row0 = (bi >> 1) * 16;
        int b, rr; float v;
        if (gemv_staged<2048, false>(g_hn, w1, 0, DD, 0, row0, bh, threadIdx.x,
                                     &b, &rr, &v)) {
            int row = row0 + rr;
            g_ff1[(size_t)b * HIDDEN + row] = v / (1.0f + __expf(-v));
        }
    } else {
        int bj = bi - (HIDDEN / 16) * 2;
        int bh = bj & 1, row0 = (bj >> 1) * 16;
        int b, rr; float v;
        if (gemv_staged<2048, false>(g_hn, w3, 0, DD, 0, row0, bh, threadIdx.x,
                                     &b, &rr, &v)) {
            int row = row0 + rr;
            g_w3o[(size_t)b * DD + row] = v;
        }
    }
}

__global__ __launch_bounds__(256, 2) void gemv_w2_kernel(const float* __restrict__ w2) {
    int bi = blockIdx.x;
    int bh = bi & 1, khB = (bi >> 1) & 1, row0 = (bi >> 2) * 16;
    int k0 = khB * (HIDDEN / 2);
    int b, rr; float v;
    if (gemv_staged<HIDDEN / 2, false>(g_ff1, w2, 0, HIDDEN, k0, row0, bh,
                                       threadIdx.x, &b, &rr, &v)) {
        int row = row0 + rr;
        g_w2p[khB][(size_t)b * DD + row] = v;
    }
}

__global__ void final_kernel(float* __restrict__ out) {
    int idx = blockIdx.x * 256 + threadIdx.x;
    if (idx >= BB * DD) return;
    out[idx] = g_h[idx] + g_w3o[idx] + g_w2p[0][idx] + g_w2p[1][idx];
}

// ---------------- attention split kernel (proven R13 version) --------------
__global__ __launch_bounds__(256) void attn_split_kernel(
    const float* __restrict__ cache_k, const float* __restrict__ cache_v) {
    int blk = blockIdx.x;
    int pair = blk / NSPLIT, split = blk % NSPLIT;
    int b = pair >> 3, kv = pair & 7;
    int t0 = split * TCHUNK;
    int tid = threadIdx.x, lane = tid & 31, wid = tid >> 5;

    __shared__ float q_s[4][64];
    __shared__ float4 e_sT[TCHUNK];
    __shared__ float red[4][8];
    __shared__ float o_part[4][4][64];

    {
        int g = tid >> 6, d = tid & 63;
        q_s[g][d] = g_q[(size_t)b * DD + (kv * 4 + g) * 64 + d] * 0.125f;
    }
    __syncthreads();

    int c = lane & 7, p = lane >> 3;
    float qr[4][8];
#pragma unroll
    for (int g = 0; g < 4; g++)
#pragma unroll
        for (int j = 0; j < 8; j++) qr[g][j] = q_s[g][c * 8 + j];

    const float* kbase = cache_k + ((size_t)b * TSEQ * NKV + kv) * HDIM;
    const float* knew  = g_k + (size_t)(b * NKV + kv) * HDIM;

    float esum[4] = {0.f, 0.f, 0.f, 0.f};
#pragma unroll
    for (int it = 0; it < TCHUNK / 32; it++) {
        int tl = it * 32 + wid * 4 + p;
        int t = t0 + tl;
        const float* krow = (t < TSEQ - 1) ? (kbase + (size_t)t * KVD) : knew;
        const float4* k4 = (const float4*)krow;
        float4 k0 = __ldcs(k4 + c * 2);
        float4 k1 = __ldcs(k4 + c * 2 + 1);
        float kv8[8] = {k0.x, k0.y, k0.z, k0.w, k1.x, k1.y, k1.z, k1.w};
        float a0 = 0.f, a1 = 0.f, a2 = 0.f, a3 = 0.f;
#pragma unroll
        for (int j = 0; j < 8; j++) {
            a0 += qr[0][j] * kv8[j];
            a1 += qr[1][j] * kv8[j];
            a2 += qr[2][j] * kv8[j];
            a3 += qr[3][j] * kv8[j];
        }
#pragma unroll
        for (int off = 1; off <= 4; off <<= 1) {
            a0 += __shfl_xor_sync(0xffffffffu, a0, off);
            a1 += __shfl_xor_sync(0xffffffffu, a1, off);
            a2 += __shfl_xor_sync(0xffffffffu, a2, off);
            a3 += __shfl_xor_sync(0xffffffffu, a3, off);
        }
        if (c == 0) {
            float4 e;
            e.x = __expf(a0); e.y = __expf(a1);
            e.z = __expf(a2); e.w = __expf(a3);
            e_sT[tl] = e;
            esum[0] += e.x; esum[1] += e.y; esum[2] += e.z; esum[3] += e.w;
        }
    }
#pragma unroll
    for (int g = 0; g < 4; g++) {
        esum[g] = warp_sum(esum[g]);
        if (lane == 0) red[g][wid] = esum[g];
    }
    __syncthreads();
    if (tid < 4) {
        float s = 0.f;
#pragma unroll
        for (int w = 0; w < 8; w++) s += red[tid][w];
        g_pl[blk * 4 + tid] = s;
    }

    {
        int qq = tid >> 6, d = tid & 63;
        const float* vcol = cache_v + ((size_t)b * TSEQ * NKV + kv) * HDIM + d;
        const float* vnew = g_v + (size_t)(b * NKV + kv) * HDIM + d;
        float o0 = 0.f, o1 = 0.f, o2 = 0.f, o3 = 0.f;
        int tlb = qq * (TCHUNK / 4);
#pragma unroll 8
        for (int i = 0; i < TCHUNK / 4; i++) {
            int tl = tlb + i;
            int t = t0 + tl;
            float v = (t < TSEQ - 1) ? __ldcs(vcol + (size_t)t * KVD) : *vnew;
            float4 pv = e_sT[tl];
            o0 += pv.x * v; o1 += pv.y * v; o2 += pv.z * v; o3 += pv.w * v;
        }
        o_part[qq][0][d] = o0;
        o_part[qq][1][d] = o1;
        o_part[qq][2][d] = o2;
        o_part[qq][3][d] = o3;
    }
    __syncthreads();
    {
        int g = tid >> 6, d = tid & 63;
        float sum = o_part[0][g][d] + o_part[1][g][d] +
                    o_part[2][g][d] + o_part[3][g][d];
        g_po[(size_t)blk * 256 + g * 64 + d] = sum;
    }
}

// ---------------- parallel reduce: grid pair*4+g, 256 thr, 4-way split -----
__global__ __launch_bounds__(256) void attn_reduce_kernel() {
    int pg = blockIdx.x;
    int pair = pg >> 2, g = pg & 3;
    int b = pair >> 3, kv = pair & 7;
    int tid = threadIdx.x, d = tid & 63, sh = tid >> 6;   // sh in 0..3
    __shared__ float s_o[4][64];
    __shared__ float s_l[4];
    float l = 0.f, o = 0.f;
#pragma unroll
    for (int i = 0; i < NSPLIT / 4; i++) {
        int s = sh * (NSPLIT / 4) + i;
        int bs = pair * NSPLIT + s;
        l += g_pl[bs * 4 + g];
        o += g_po[(size_t)bs * 256 + g * 64 + d];
    }
    s_o[sh][d] = o;
    if (d == 0) s_l[sh] = l;
    __syncthreads();
    if (sh == 0) {
        float L = s_l[0] + s_l[1] + s_l[2] + s_l[3];
        float O = o + s_o[1][d] + s_o[2][d] + s_o[3][d];
        g_attn[(size_t)b * DD + (kv * 4 + g) * 64 + d] = O / L;
    }
}

// ---------------- launch ----------------
extern "C" void kernel_launch(void* const* d_in, const int* in_sizes, int n_in,
                              void* d_out, int out_size) {
    const float* x         = (const float*)d_in[0];
    const float* freqs_cos = (const float*)d_in[1];
    const float* freqs_sin = (const float*)d_in[2];
    const float* cache_k   = (const float*)d_in[3];
    const float* cache_v   = (const float*)d_in[4];
    const float* wq_w      = (const float*)d_in[5];
    const float* wk_w      = (const float*)d_in[6];
    const float* wv_w      = (const float*)d_in[7];
    const float* wo_w      = (const float*)d_in[8];
    const float* w1_w      = (const float*)d_in[9];
    const float* w2_w      = (const float*)d_in[10];
    const float* w3_w      = (const float*)d_in[11];
    const float* attn_nw   = (const float*)d_in[12];
    const float* ffn_nw    = (const float*)d_in[13];
    float* out = (float*)d_out;

    const int SMEM_STD = (8 * 2048 + 256) * 4;          // 66560
    const int SMEM_W2  = (8 * (HIDDEN / 2) + 256) * 4;  // 91136
    cudaFuncSetAttribute(gemv_qkv_kernel,  cudaFuncAttributeMaxDynamicSharedMemorySize, SMEM_STD);
    cudaFuncSetAttribute(gemv_wo_kernel,   cudaFuncAttributeMaxDynamicSharedMemorySize, SMEM_STD);
    cudaFuncSetAttribute(gemv_w1w3_kernel, cudaFuncAttributeMaxDynamicSharedMemorySize, SMEM_STD);
    cudaFuncSetAttribute(gemv_w2_kernel,   cudaFuncAttributeMaxDynamicSharedMemorySize, SMEM_W2);

    sumsq_x_kernel<<<BB, 512>>>(x);
    gemv_qkv_kernel<<<(3072 / 16) * 2, 256, SMEM_STD>>>(x, attn_nw, wq_w, wk_w,
                                                        wv_w, freqs_cos, freqs_sin);
    attn_split_kernel<<<BB * NKV * NSPLIT, 256>>>(cache_k, cache_v);
    attn_reduce_kernel<<<BB * NKV * GRP, 256>>>();
    gemv_wo_kernel<<<(DD / 16) * 2, 256, SMEM_STD>>>(wo_w, x);
    rmsnorm_h_kernel<<<BB, 512>>>(ffn_nw);
    gemv_w1w3_kernel<<<(HIDDEN / 16) * 2 + (DD / 16) * 2, 256, SMEM_STD>>>(w1_w, w3_w);
    gemv_w2_kernel<<<(DD / 16) * 4, 256, SMEM_W2>>>(w2_w);
    final_kernel<<<(BB * DD + 255) / 256, 256>>>(out);
}